// round 2
// baseline (speedup 1.0000x reference)
#include <cuda_runtime.h>
#include <cuda_bf16.h>
#include <math.h>

#define T 2048
#define H 1024
#define F 2816
#define E 8
#define BK 32

// ---------------- scratch (__device__ globals: allocation-free rule) --------
__device__ int   g_cnt[E];
__device__ int   g_tok[E * T];
__device__ float g_wt [E * T];
__device__ float g_x[(size_t)T * H];            // tf32-pre-rounded x (8 MB)
__device__ float g_h[(size_t)E * T * F];        // tf32-pre-rounded hidden (184 MB)

// ---------------- helpers ---------------------------------------------------
__device__ __forceinline__ unsigned f2tf(float v) {
    unsigned r;
    asm("cvt.rna.tf32.f32 %0, %1;" : "=r"(r) : "f"(v));
    return r;
}
__device__ __forceinline__ float f2tf_f(float v) { return __uint_as_float(f2tf(v)); }

__device__ __forceinline__ void mma_tf32(float d[4], const unsigned a[4],
                                         const unsigned b[2]) {
    asm volatile(
        "mma.sync.aligned.m16n8k8.row.col.f32.tf32.tf32.f32 "
        "{%0,%1,%2,%3}, {%4,%5,%6,%7}, {%8,%9}, {%0,%1,%2,%3};\n"
        : "+f"(d[0]), "+f"(d[1]), "+f"(d[2]), "+f"(d[3])
        : "r"(a[0]), "r"(a[1]), "r"(a[2]), "r"(a[3]),
          "r"(b[0]), "r"(b[1]));
}

__device__ __forceinline__ void cpa16(float* dst, const float* src) {
    unsigned s = (unsigned)__cvta_generic_to_shared(dst);
    asm volatile("cp.async.cg.shared.global [%0], [%1], 16;" :: "r"(s), "l"(src));
}
#define CP_COMMIT() asm volatile("cp.async.commit_group;")
#define CP_WAIT1()  asm volatile("cp.async.wait_group 1;")

// ---------------- kernel 0: init (zero out, round x, reset counters) --------
__global__ void k_init(const float* __restrict__ x, float* out) {
    int n = T * H;
    for (int i = blockIdx.x * blockDim.x + threadIdx.x; i < n;
         i += gridDim.x * blockDim.x) {
        out[i] = 0.0f;
        g_x[i] = f2tf_f(x[i]);
    }
    if (blockIdx.x == 0 && threadIdx.x < E) g_cnt[threadIdx.x] = 0;
}

// ---------------- kernel 1: router (one warp per token) ---------------------
__global__ void k_router(const float* __restrict__ x,
                         const float* __restrict__ gw) {
    int warp = (blockIdx.x * blockDim.x + threadIdx.x) >> 5;
    int lane = threadIdx.x & 31;
    if (warp >= T) return;
    const float* xr = x + (size_t)warp * H;
    float logit[E];
#pragma unroll
    for (int e = 0; e < E; e++) {
        const float* g = gw + (size_t)e * H;
        float p = 0.0f;
        for (int k = lane; k < H; k += 32) p += xr[k] * g[k];
#pragma unroll
        for (int o = 16; o; o >>= 1) p += __shfl_xor_sync(0xffffffffu, p, o);
        logit[e] = p;
    }
    if (lane == 0) {
        int i0 = 0; float v0 = logit[0];
#pragma unroll
        for (int e = 1; e < E; e++)
            if (logit[e] > v0) { v0 = logit[e]; i0 = e; }
        int i1 = -1; float v1 = -3.0e38f;
#pragma unroll
        for (int e = 0; e < E; e++)
            if (e != i0 && logit[e] > v1) { v1 = logit[e]; i1 = e; }
        float w0 = 1.0f / (1.0f + expf(v1 - v0));
        float w1 = 1.0f - w0;
        int p0 = atomicAdd(&g_cnt[i0], 1);
        g_tok[i0 * T + p0] = warp; g_wt[i0 * T + p0] = w0;
        int p1 = atomicAdd(&g_cnt[i1], 1);
        g_tok[i1 * T + p1] = warp; g_wt[i1 * T + p1] = w1;
    }
}

// ---------------- kernel 2: GEMM1 (x@w1^T, x@w3^T) + SwiGLU -> g_h ----------
// grid (F/64, T/128, E), block 256. BM=128, BN=64. Warp tile 32x32.
__global__ __launch_bounds__(256, 2)
void k_gemm1(const float* __restrict__ w1, const float* __restrict__ w3) {
    int e = blockIdx.z;
    int cnt = g_cnt[e];
    int m0 = blockIdx.y * 128;
    if (m0 >= cnt) return;
    int n0 = blockIdx.x * 64;

    extern __shared__ float sm[];
    float* As = sm;                       // [2][128*36]
    float* B1 = sm + 2 * 128 * 36;        // [2][64*36]
    float* B2 = B1 + 2 * 64 * 36;         // [2][64*36]
    int* toks = (int*)(B2 + 2 * 64 * 36); // [128]

    int tid = threadIdx.x, wid = tid >> 5, lane = tid & 31;
    int wm = (wid & 3) * 32, wn = (wid >> 2) * 32;
    int lr = lane >> 2, lc = lane & 3;

    if (tid < 128) toks[tid] = g_tok[e * T + min(m0 + tid, cnt - 1)];
    __syncthreads();

    const float* w1e = w1 + (size_t)e * F * H + (size_t)n0 * H;
    const float* w3e = w3 + (size_t)e * F * H + (size_t)n0 * H;

    float accG[2][4][4] = {};
    float accU[2][4][4] = {};

    auto load = [&](int st, int k0) {
        float* A  = As + st * (128 * 36);
        float* b1 = B1 + st * (64 * 36);
        float* b2 = B2 + st * (64 * 36);
#pragma unroll
        for (int q = 0; q < 4; q++) {                // A: 1024 x 16B chunks
            int f = tid + q * 256;
            int r = f >> 3, c4 = (f & 7) * 4;
            cpa16(&A[r * 36 + c4], g_x + (size_t)toks[r] * H + k0 + c4);
        }
#pragma unroll
        for (int q = 0; q < 2; q++) {                // B1/B2: 512 chunks each
            int f = tid + q * 256;
            int r = f >> 3, c4 = (f & 7) * 4;
            cpa16(&b1[r * 36 + c4], w1e + (size_t)r * H + k0 + c4);
            cpa16(&b2[r * 36 + c4], w3e + (size_t)r * H + k0 + c4);
        }
    };

    load(0, 0);
    CP_COMMIT();
    const int NIT = H / BK;   // 32
    for (int it = 0; it < NIT; ++it) {
        int cur = it & 1;
        if (it + 1 < NIT) load(cur ^ 1, (it + 1) * BK);
        CP_COMMIT();
        CP_WAIT1();
        __syncthreads();

        const float* A   = As + cur * (128 * 36);
        const float* b1s = B1 + cur * (64 * 36);
        const float* b2s = B2 + cur * (64 * 36);
#pragma unroll
        for (int kk = 0; kk < BK; kk += 8) {
            unsigned a[2][4];
#pragma unroll
            for (int i = 0; i < 2; i++) {
                int r = (wm + i * 16 + lr) * 36 + kk + lc;
                a[i][0] = __float_as_uint(A[r]);
                a[i][1] = __float_as_uint(A[r + 8 * 36]);
                a[i][2] = __float_as_uint(A[r + 4]);
                a[i][3] = __float_as_uint(A[r + 8 * 36 + 4]);
            }
#pragma unroll
            for (int j = 0; j < 4; j++) {
                int n = (wn + j * 8 + lr) * 36 + kk + lc;
                unsigned b1v[2], b2v[2];
                b1v[0] = f2tf(b1s[n]);     b1v[1] = f2tf(b1s[n + 4]);
                b2v[0] = f2tf(b2s[n]);     b2v[1] = f2tf(b2s[n + 4]);
#pragma unroll
                for (int i = 0; i < 2; i++) {
                    mma_tf32(accG[i][j], a[i], b1v);
                    mma_tf32(accU[i][j], a[i], b2v);
                }
            }
        }
        __syncthreads();
    }

    // epilogue: h = silu(g)*u, tf32-round, store to padded scratch
#pragma unroll
    for (int i = 0; i < 2; i++) {
#pragma unroll
        for (int p = 0; p < 2; p++) {
            int rr = wm + i * 16 + p * 8 + lr;
            size_t row = (size_t)(e * T + m0 + rr);
#pragma unroll
            for (int j = 0; j < 4; j++) {
                float g0 = accG[i][j][p * 2 + 0], g1 = accG[i][j][p * 2 + 1];
                float u0 = accU[i][j][p * 2 + 0], u1 = accU[i][j][p * 2 + 1];
                float h0 = g0 / (1.0f + __expf(-g0)) * u0;
                float h1 = g1 / (1.0f + __expf(-g1)) * u1;
                float2 st; st.x = f2tf_f(h0); st.y = f2tf_f(h1);
                *(float2*)&g_h[row * F + n0 + wn + j * 8 + 2 * lc] = st;
            }
        }
    }
}

// ---------------- kernel 3: GEMM2 (h@w2^T) + weighted scatter ---------------
// grid (H/128, T/128, E), block 256. BM=128, BN=128. Warp tile 64x32.
__global__ __launch_bounds__(256, 2)
void k_gemm2(const float* __restrict__ w2, float* __restrict__ out) {
    int e = blockIdx.z;
    int cnt = g_cnt[e];
    int m0 = blockIdx.y * 128;
    if (m0 >= cnt) return;
    int n0 = blockIdx.x * 128;

    extern __shared__ float sm[];
    float* As = sm;                   // [2][128*36]
    float* Bs = sm + 2 * 128 * 36;    // [2][128*36]

    int tid = threadIdx.x, wid = tid >> 5, lane = tid & 31;
    int wm = (wid & 1) * 64, wn = (wid >> 1) * 32;
    int lr = lane >> 2, lc = lane & 3;

    const float* w2e   = w2 + (size_t)e * H * F + (size_t)n0 * F;
    const float* hbase = &g_h[(size_t)(e * T + m0) * F];

    float acc[4][4][4] = {};

    auto load = [&](int st, int k0) {
        float* A = As + st * (128 * 36);
        float* B = Bs + st * (128 * 36);
#pragma unroll
        for (int q = 0; q < 4; q++) {
            int f = tid + q * 256;
            int r = f >> 3, c4 = (f & 7) * 4;
            cpa16(&A[r * 36 + c4], hbase + (size_t)r * F + k0 + c4);
            cpa16(&B[r * 36 + c4], w2e + (size_t)r * F + k0 + c4);
        }
    };

    load(0, 0);
    CP_COMMIT();
    const int NIT = F / BK;   // 88
    for (int it = 0; it < NIT; ++it) {
        int cur = it & 1;
        if (it + 1 < NIT) load(cur ^ 1, (it + 1) * BK);
        CP_COMMIT();
        CP_WAIT1();
        __syncthreads();

        const float* A = As + cur * (128 * 36);
        const float* B = Bs + cur * (128 * 36);
#pragma unroll
        for (int kk = 0; kk < BK; kk += 8) {
            unsigned a[4][4];
#pragma unroll
            for (int i = 0; i < 4; i++) {
                int r = (wm + i * 16 + lr) * 36 + kk + lc;
                a[i][0] = __float_as_uint(A[r]);
                a[i][1] = __float_as_uint(A[r + 8 * 36]);
                a[i][2] = __float_as_uint(A[r + 4]);
                a[i][3] = __float_as_uint(A[r + 8 * 36 + 4]);
            }
#pragma unroll
            for (int j = 0; j < 4; j++) {
                int n = (wn + j * 8 + lr) * 36 + kk + lc;
                unsigned b[2];
                b[0] = f2tf(B[n]); b[1] = f2tf(B[n + 4]);
#pragma unroll
                for (int i = 0; i < 4; i++) mma_tf32(acc[i][j], a[i], b);
            }
        }
        __syncthreads();
    }

    // epilogue: weighted scatter-add into out
#pragma unroll
    for (int i = 0; i < 4; i++) {
#pragma unroll
        for (int p = 0; p < 2; p++) {
            int rr = wm + i * 16 + p * 8 + lr;
            int rg = m0 + rr;
            if (rg >= cnt) continue;
            int   tok = g_tok[e * T + rg];
            float w   = g_wt [e * T + rg];
            float* orow = out + (size_t)tok * H;
#pragma unroll
            for (int j = 0; j < 4; j++) {
                int col = n0 + wn + j * 8 + 2 * lc;
                atomicAdd(&orow[col    ], w * acc[i][j][p * 2 + 0]);
                atomicAdd(&orow[col + 1], w * acc[i][j][p * 2 + 1]);
            }
        }
    }
}

// ---------------- launch ----------------------------------------------------
extern "C" void kernel_launch(void* const* d_in, const int* in_sizes, int n_in,
                              void* d_out, int out_size) {
    const float* x    = (const float*)d_in[0];   // [T, H]
    const float* gw   = (const float*)d_in[1];   // [E, H]
    const float* w1   = (const float*)d_in[2];   // [E, F, H]
    const float* w3   = (const float*)d_in[3];   // [E, F, H]
    const float* w2   = (const float*)d_in[4];   // [E, H, F]
    float* out = (float*)d_out;                  // [T, H]

    static const int SMEM1 = (2 * 128 * 36 + 4 * 64 * 36) * 4 + 128 * 4;  // 74240
    static const int SMEM2 = (4 * 128 * 36) * 4;                          // 73728
    cudaFuncSetAttribute(k_gemm1, cudaFuncAttributeMaxDynamicSharedMemorySize, SMEM1);
    cudaFuncSetAttribute(k_gemm2, cudaFuncAttributeMaxDynamicSharedMemorySize, SMEM2);

    k_init<<<512, 256>>>(x, out);
    k_router<<<T / 8, 256>>>(x, gw);
    dim3 g1(F / 64, T / 128, E);
    k_gemm1<<<g1, 256, SMEM1>>>(w1, w3);
    dim3 g2(H / 128, T / 128, E);
    k_gemm2<<<g2, 256, SMEM2>>>(w2, out);
}

// round 5
// speedup vs baseline: 1.9103x; 1.9103x over previous
#include <cuda_runtime.h>
#include <cuda_fp16.h>
#include <math.h>
#include <stdint.h>

#define T 2048
#define H 1024
#define F 2816
#define E 8
#define S 3            // cp.async pipeline stages
#define BK 32          // k (f16 elems) per stage
#define ASTRIDE 40     // padded row stride in f16 (80 bytes)

// ---------------- scratch (__device__ globals: allocation-free rule) --------
__device__ int    g_cnt[E];
__device__ int    g_tok[E * T];
__device__ float  g_wt [E * T];
__device__ int    g_inv[2 * T];                 // token -> slot (e*T+p)
__device__ __half g_xh [(size_t)T * H];         // fp16 x
__device__ __half g_hh [(size_t)E * T * F];     // fp16 hidden
__device__ __half g_w1h[(size_t)E * F * H];
__device__ __half g_w3h[(size_t)E * F * H];
__device__ __half g_w2h[(size_t)E * H * F];
__device__ float  g_y  [(size_t)E * T * H];     // unweighted expert outputs

// ---------------- helpers ---------------------------------------------------
__device__ __forceinline__ unsigned h2u(__half2 h) {
    union { __half2 h; unsigned u; } c; c.h = h; return c.u;
}
__device__ __forceinline__ void mma_f16(float d[4], const unsigned a[4],
                                        const unsigned b[2]) {
    asm volatile(
        "mma.sync.aligned.m16n8k16.row.col.f32.f16.f16.f32 "
        "{%0,%1,%2,%3}, {%4,%5,%6,%7}, {%8,%9}, {%0,%1,%2,%3};\n"
        : "+f"(d[0]), "+f"(d[1]), "+f"(d[2]), "+f"(d[3])
        : "r"(a[0]), "r"(a[1]), "r"(a[2]), "r"(a[3]),
          "r"(b[0]), "r"(b[1]));
}
__device__ __forceinline__ void ldsm4(unsigned r[4], uint32_t addr) {
    asm volatile("ldmatrix.sync.aligned.m8n8.x4.shared.b16 {%0,%1,%2,%3}, [%4];"
                 : "=r"(r[0]), "=r"(r[1]), "=r"(r[2]), "=r"(r[3]) : "r"(addr));
}
__device__ __forceinline__ void cpa16(uint32_t dst, const void* src) {
    asm volatile("cp.async.cg.shared.global [%0], [%1], 16;" :: "r"(dst), "l"(src));
}
#define CP_COMMIT() asm volatile("cp.async.commit_group;")
#define CP_WAIT1()  asm volatile("cp.async.wait_group 1;")
__device__ __forceinline__ uint32_t smem_u32(const void* p) {
    return (uint32_t)__cvta_generic_to_shared(p);
}

#define TILE0 1024
#define A_BYTES (128 * ASTRIDE * 2)              // 10240
#define STAGE_B (2 * A_BYTES)                    // 20480 (A + B-region)
#define SMEM_SZ (TILE0 + S * STAGE_B)            // 62464

// ---------------- kernel: prep (fp32 weights -> fp16) -----------------------
__global__ void k_prep(const float* __restrict__ w1, const float* __restrict__ w3,
                       const float* __restrict__ w2) {
    const size_t n4 = (size_t)E * F * H / 4;
    size_t stride = (size_t)gridDim.x * blockDim.x;
    for (size_t i = blockIdx.x * (size_t)blockDim.x + threadIdx.x; i < n4; i += stride) {
        float4 a = ((const float4*)w1)[i];
        uint2 pa; pa.x = h2u(__floats2half2_rn(a.x, a.y));
        pa.y = h2u(__floats2half2_rn(a.z, a.w));
        ((uint2*)g_w1h)[i] = pa;
        float4 b = ((const float4*)w3)[i];
        uint2 pb; pb.x = h2u(__floats2half2_rn(b.x, b.y));
        pb.y = h2u(__floats2half2_rn(b.z, b.w));
        ((uint2*)g_w3h)[i] = pb;
        float4 c = ((const float4*)w2)[i];
        uint2 pc; pc.x = h2u(__floats2half2_rn(c.x, c.y));
        pc.y = h2u(__floats2half2_rn(c.z, c.w));
        ((uint2*)g_w2h)[i] = pc;
    }
}

// ---------------- kernel: init (x -> fp16, counters) ------------------------
__global__ void k_init(const float* __restrict__ x) {
    const int n4 = T * H / 4;
    for (int i = blockIdx.x * blockDim.x + threadIdx.x; i < n4;
         i += gridDim.x * blockDim.x) {
        float4 a = ((const float4*)x)[i];
        uint2 p; p.x = h2u(__floats2half2_rn(a.x, a.y));
        p.y = h2u(__floats2half2_rn(a.z, a.w));
        ((uint2*)g_xh)[i] = p;
    }
    if (blockIdx.x == 0 && threadIdx.x < E) g_cnt[threadIdx.x] = 0;
}

// ---------------- kernel: router --------------------------------------------
__global__ void k_router(const float* __restrict__ x, const float* __restrict__ gw) {
    int warp = (blockIdx.x * blockDim.x + threadIdx.x) >> 5;
    int lane = threadIdx.x & 31;
    if (warp >= T) return;
    const float* xr = x + (size_t)warp * H;
    float logit[E];
#pragma unroll
    for (int e = 0; e < E; e++) {
        const float* g = gw + (size_t)e * H;
        float p = 0.0f;
        for (int k = lane; k < H; k += 32) p += xr[k] * g[k];
#pragma unroll
        for (int o = 16; o; o >>= 1) p += __shfl_xor_sync(0xffffffffu, p, o);
        logit[e] = p;
    }
    if (lane == 0) {
        int i0 = 0; float v0 = logit[0];
#pragma unroll
        for (int e = 1; e < E; e++)
            if (logit[e] > v0) { v0 = logit[e]; i0 = e; }
        int i1 = -1; float v1 = -3.0e38f;
#pragma unroll
        for (int e = 0; e < E; e++)
            if (e != i0 && logit[e] > v1) { v1 = logit[e]; i1 = e; }
        float w0 = 1.0f / (1.0f + expf(v1 - v0));
        float w1 = 1.0f - w0;
        int p0 = atomicAdd(&g_cnt[i0], 1);
        g_tok[i0 * T + p0] = warp; g_wt[i0 * T + p0] = w0;
        g_inv[2 * warp + 0] = i0 * T + p0;
        int p1 = atomicAdd(&g_cnt[i1], 1);
        g_tok[i1 * T + p1] = warp; g_wt[i1 * T + p1] = w1;
        g_inv[2 * warp + 1] = i1 * T + p1;
    }
}

// ---------------- kernel: GEMM1 (fp16 mma): SwiGLU -> g_hh ------------------
// grid (F/64, T/128, E), block 256. Block tile 128x64 (g and u). Warp 32x32.
__global__ __launch_bounds__(256, 2)
void k_gemm1() {
    int e = blockIdx.z;
    int cnt = g_cnt[e];
    int m0 = blockIdx.y * 128;
    if (m0 >= cnt) return;
    int n0 = blockIdx.x * 64;

    extern __shared__ char sm[];
    int* toks = (int*)sm;
    uint32_t sb = smem_u32(sm);

    int tid = threadIdx.x, wid = tid >> 5, lane = tid & 31;
    int wm = (wid & 3) * 32, wn = (wid >> 2) * 32;
    int lr = lane >> 2, lc = lane & 3;

    if (tid < 128) toks[tid] = g_tok[e * T + min(m0 + tid, cnt - 1)];
    __syncthreads();

    const __half* w1e = g_w1h + ((size_t)e * F + n0) * H;
    const __half* w3e = g_w3h + ((size_t)e * F + n0) * H;

    float accG[2][4][4] = {};
    float accU[2][4][4] = {};

    // stage layout: A rows [0,128) at abase, B1 rows [0,64) then B2 rows [0,64)
    auto load_tile = [&](int s, int itile) {
        uint32_t abase = sb + TILE0 + s * STAGE_B;
        uint32_t bbase = abase + A_BYTES;
        int k0 = itile * BK;
        // A: 128 rows x 4 chunks = 512 chunks; 256 thr -> 2 each
#pragma unroll
        for (int q = 0; q < 2; q++) {
            int ch = tid + q * 256;
            int r = ch >> 2, c = ch & 3;
            cpa16(abase + r * 80 + c * 16, g_xh + (size_t)toks[r] * H + k0 + c * 8);
        }
        // B1+B2: 64 rows x 4 chunks each = 512 chunks
#pragma unroll
        for (int q = 0; q < 2; q++) {
            int ch = tid + q * 256;
            int half_sel = ch >> 8;              // 0: B1, 1: B2
            int r = (ch >> 2) & 63, c = ch & 3;
            const __half* src = half_sel ? (w3e + (size_t)r * H + k0 + c * 8)
                                         : (w1e + (size_t)r * H + k0 + c * 8);
            cpa16(bbase + half_sel * (64 * 80) + r * 80 + c * 16, src);
        }
    };

    load_tile(0, 0); CP_COMMIT();
    load_tile(1, 1); CP_COMMIT();

    const int NIT = H / BK;   // 32
    for (int it = 0; it < NIT; ++it) {
        CP_WAIT1();
        __syncthreads();
        if (it + 2 < NIT) load_tile((it + 2) % S, it + 2);
        CP_COMMIT();

        uint32_t abase = sb + TILE0 + (it % S) * STAGE_B;
        uint32_t bbase = abase + A_BYTES;
#pragma unroll
        for (int kk = 0; kk < BK; kk += 16) {
            unsigned a[2][4];
#pragma unroll
            for (int i = 0; i < 2; i++) {
                uint32_t ad = abase + (wm + i * 16 + (lane & 15)) * 80
                            + kk * 2 + ((lane >> 4) << 4);
                ldsm4(a[i], ad);
            }
#pragma unroll
            for (int j = 0; j < 4; j++) {
                uint32_t brow1 = bbase + (wn + j * 8 + lr) * 80 + kk * 2 + lc * 4;
                uint32_t brow2 = brow1 + 64 * 80;
                unsigned b1[2], b2[2];
                asm volatile("ld.shared.b32 %0, [%1];" : "=r"(b1[0]) : "r"(brow1));
                asm volatile("ld.shared.b32 %0, [%1];" : "=r"(b1[1]) : "r"(brow1 + 16));
                asm volatile("ld.shared.b32 %0, [%1];" : "=r"(b2[0]) : "r"(brow2));
                asm volatile("ld.shared.b32 %0, [%1];" : "=r"(b2[1]) : "r"(brow2 + 16));
#pragma unroll
                for (int i = 0; i < 2; i++) {
                    mma_f16(accG[i][j], a[i], b1);
                    mma_f16(accU[i][j], a[i], b2);
                }
            }
        }
        __syncthreads();
    }

    // epilogue: h = silu(g)*u -> fp16
#pragma unroll
    for (int i = 0; i < 2; i++) {
#pragma unroll
        for (int p = 0; p < 2; p++) {
            int rr = wm + i * 16 + p * 8 + lr;
            size_t row = (size_t)(e * T + m0 + rr) * F + n0;
#pragma unroll
            for (int j = 0; j < 4; j++) {
                float g0 = accG[i][j][p * 2 + 0], g1 = accG[i][j][p * 2 + 1];
                float u0 = accU[i][j][p * 2 + 0], u1 = accU[i][j][p * 2 + 1];
                float h0 = g0 / (1.0f + __expf(-g0)) * u0;
                float h1 = g1 / (1.0f + __expf(-g1)) * u1;
                *(__half2*)&g_hh[row + wn + j * 8 + 2 * lc] = __floats2half2_rn(h0, h1);
            }
        }
    }
}

// ---------------- kernel: GEMM2 (fp16 mma): y = h @ w2^T --------------------
// grid (H/128, T/128, E), block 256. Block tile 128x128. Warp 64x32.
__global__ __launch_bounds__(256, 2)
void k_gemm2() {
    int e = blockIdx.z;
    int cnt = g_cnt[e];
    int m0 = blockIdx.y * 128;
    if (m0 >= cnt) return;
    int n0 = blockIdx.x * 128;

    extern __shared__ char sm[];
    uint32_t sb = smem_u32(sm);

    int tid = threadIdx.x, wid = tid >> 5, lane = tid & 31;
    int wm = (wid & 1) * 64, wn = (wid >> 1) * 32;
    int lr = lane >> 2, lc = lane & 3;

    const __half* hbase = g_hh + (size_t)(e * T + m0) * F;
    const __half* w2e   = g_w2h + ((size_t)e * H + n0) * F;

    float acc[4][4][4] = {};

    auto load_tile = [&](int s, int itile) {
        uint32_t abase = sb + TILE0 + s * STAGE_B;
        uint32_t bbase = abase + A_BYTES;
        int k0 = itile * BK;
#pragma unroll
        for (int q = 0; q < 2; q++) {
            int ch = tid + q * 256;
            int r = ch >> 2, c = ch & 3;
            cpa16(abase + r * 80 + c * 16, hbase + (size_t)r * F + k0 + c * 8);
            cpa16(bbase + r * 80 + c * 16, w2e + (size_t)r * F + k0 + c * 8);
        }
    };

    load_tile(0, 0); CP_COMMIT();
    load_tile(1, 1); CP_COMMIT();

    const int NIT = F / BK;   // 88
    for (int it = 0; it < NIT; ++it) {
        CP_WAIT1();
        __syncthreads();
        if (it + 2 < NIT) load_tile((it + 2) % S, it + 2);
        CP_COMMIT();

        uint32_t abase = sb + TILE0 + (it % S) * STAGE_B;
        uint32_t bbase = abase + A_BYTES;
#pragma unroll
        for (int kk = 0; kk < BK; kk += 16) {
            unsigned a[4][4];
#pragma unroll
            for (int i = 0; i < 4; i++) {
                uint32_t ad = abase + (wm + i * 16 + (lane & 15)) * 80
                            + kk * 2 + ((lane >> 4) << 4);
                ldsm4(a[i], ad);
            }
#pragma unroll
            for (int j = 0; j < 4; j++) {
                uint32_t brow = bbase + (wn + j * 8 + lr) * 80 + kk * 2 + lc * 4;
                unsigned b[2];
                asm volatile("ld.shared.b32 %0, [%1];" : "=r"(b[0]) : "r"(brow));
                asm volatile("ld.shared.b32 %0, [%1];" : "=r"(b[1]) : "r"(brow + 16));
#pragma unroll
                for (int i = 0; i < 4; i++) mma_f16(acc[i][j], a[i], b);
            }
        }
        __syncthreads();
    }

    // epilogue: plain stores of unweighted y (combine kernel applies weights)
#pragma unroll
    for (int i = 0; i < 4; i++) {
#pragma unroll
        for (int p = 0; p < 2; p++) {
            int rr = wm + i * 16 + p * 8 + lr;
            size_t row = (size_t)(e * T + m0 + rr) * H + n0;
#pragma unroll
            for (int j = 0; j < 4; j++) {
                float2 st;
                st.x = acc[i][j][p * 2 + 0];
                st.y = acc[i][j][p * 2 + 1];
                *(float2*)&g_y[row + wn + j * 8 + 2 * lc] = st;
            }
        }
    }
}

// ---------------- kernel: combine (out = w0*y[s0] + w1*y[s1]) ---------------
__global__ void k_combine(float* __restrict__ out) {
    int idx = blockIdx.x * blockDim.x + threadIdx.x;   // one float4
    if (idx >= T * H / 4) return;
    int t = idx / (H / 4);
    int c = idx % (H / 4);
    int s0 = g_inv[2 * t], s1 = g_inv[2 * t + 1];
    float w0 = g_wt[s0], w1 = g_wt[s1];
    float4 a = *(const float4*)&g_y[(size_t)s0 * H + c * 4];
    float4 b = *(const float4*)&g_y[(size_t)s1 * H + c * 4];
    float4 o;
    o.x = w0 * a.x + w1 * b.x;
    o.y = w0 * a.y + w1 * b.y;
    o.z = w0 * a.z + w1 * b.z;
    o.w = w0 * a.w + w1 * b.w;
    ((float4*)out)[idx] = o;
}

// ---------------- launch ----------------------------------------------------
extern "C" void kernel_launch(void* const* d_in, const int* in_sizes, int n_in,
                              void* d_out, int out_size) {
    const float* x  = (const float*)d_in[0];   // [T, H]
    const float* gw = (const float*)d_in[1];   // [E, H]
    const float* w1 = (const float*)d_in[2];   // [E, F, H]
    const float* w3 = (const float*)d_in[3];   // [E, F, H]
    const float* w2 = (const float*)d_in[4];   // [E, H, F]
    float* out = (float*)d_out;                // [T, H]

    cudaFuncSetAttribute(k_gemm1, cudaFuncAttributeMaxDynamicSharedMemorySize, SMEM_SZ);
    cudaFuncSetAttribute(k_gemm2, cudaFuncAttributeMaxDynamicSharedMemorySize, SMEM_SZ);

    k_init<<<256, 256>>>(x);
    k_router<<<T / 8, 256>>>(x, gw);
    k_prep<<<1024, 256>>>(w1, w3, w2);
    dim3 g1(F / 64, T / 128, E);
    k_gemm1<<<g1, 256, SMEM_SZ>>>();
    dim3 g2(H / 128, T / 128, E);
    k_gemm2<<<g2, 256, SMEM_SZ>>>();
    k_combine<<<(T * H / 4 + 255) / 256, 256>>>(out);
}

// round 6
// speedup vs baseline: 2.0391x; 1.0674x over previous
#include <cuda_runtime.h>
#include <cuda_fp16.h>
#include <math.h>
#include <stdint.h>

#define T 2048
#define H 1024
#define F 2816
#define E 8
#define S 3            // cp.async pipeline stages
#define BK 32          // k (f16 elems) per stage
#define ASTRIDE 40     // padded row stride in f16 (80 bytes)

// ---------------- scratch (__device__ globals: allocation-free rule) --------
__device__ int    g_cnt[E];
__device__ int    g_tok[E * T];
__device__ float  g_wt [E * T];
__device__ int    g_inv[2 * T];                 // token -> slot (e*T+p)
__device__ __half g_xh [(size_t)T * H];         // fp16 x
__device__ __half g_hh [(size_t)E * T * F];     // fp16 hidden
__device__ __half g_w1h[(size_t)E * F * H];
__device__ __half g_w3h[(size_t)E * F * H];
__device__ __half g_w2h[(size_t)E * H * F];
__device__ float  g_y  [(size_t)E * T * H];     // unweighted expert outputs

// ---------------- helpers ---------------------------------------------------
__device__ __forceinline__ unsigned h2u(__half2 h) {
    union { __half2 h; unsigned u; } c; c.h = h; return c.u;
}
__device__ __forceinline__ void mma_f16(float d[4], const unsigned a[4],
                                        const unsigned b[2]) {
    asm volatile(
        "mma.sync.aligned.m16n8k16.row.col.f32.f16.f16.f32 "
        "{%0,%1,%2,%3}, {%4,%5,%6,%7}, {%8,%9}, {%0,%1,%2,%3};\n"
        : "+f"(d[0]), "+f"(d[1]), "+f"(d[2]), "+f"(d[3])
        : "r"(a[0]), "r"(a[1]), "r"(a[2]), "r"(a[3]),
          "r"(b[0]), "r"(b[1]));
}
__device__ __forceinline__ void ldsm4(unsigned r[4], uint32_t addr) {
    asm volatile("ldmatrix.sync.aligned.m8n8.x4.shared.b16 {%0,%1,%2,%3}, [%4];"
                 : "=r"(r[0]), "=r"(r[1]), "=r"(r[2]), "=r"(r[3]) : "r"(addr));
}
__device__ __forceinline__ void cpa16(uint32_t dst, const void* src) {
    asm volatile("cp.async.cg.shared.global [%0], [%1], 16;" :: "r"(dst), "l"(src));
}
#define CP_COMMIT() asm volatile("cp.async.commit_group;")
#define CP_WAIT1()  asm volatile("cp.async.wait_group 1;")
__device__ __forceinline__ uint32_t smem_u32(const void* p) {
    return (uint32_t)__cvta_generic_to_shared(p);
}

#define TILE0 1024
#define A_BYTES (128 * ASTRIDE * 2)              // 10240
#define STAGE_B (2 * A_BYTES)                    // 20480 (A + B-region)
#define SMEM_SZ (TILE0 + S * STAGE_B)            // 62464

// ---------------- kernel: prep (fp32 weights -> fp16) -----------------------
__global__ void k_prep(const float* __restrict__ w1, const float* __restrict__ w3,
                       const float* __restrict__ w2) {
    const size_t n4 = (size_t)E * F * H / 4;
    size_t stride = (size_t)gridDim.x * blockDim.x;
    for (size_t i = blockIdx.x * (size_t)blockDim.x + threadIdx.x; i < n4; i += stride) {
        float4 a = ((const float4*)w1)[i];
        uint2 pa; pa.x = h2u(__floats2half2_rn(a.x, a.y));
        pa.y = h2u(__floats2half2_rn(a.z, a.w));
        ((uint2*)g_w1h)[i] = pa;
        float4 b = ((const float4*)w3)[i];
        uint2 pb; pb.x = h2u(__floats2half2_rn(b.x, b.y));
        pb.y = h2u(__floats2half2_rn(b.z, b.w));
        ((uint2*)g_w3h)[i] = pb;
        float4 c = ((const float4*)w2)[i];
        uint2 pc; pc.x = h2u(__floats2half2_rn(c.x, c.y));
        pc.y = h2u(__floats2half2_rn(c.z, c.w));
        ((uint2*)g_w2h)[i] = pc;
    }
}

// ---------------- kernel: init (x -> fp16, counters) ------------------------
__global__ void k_init(const float* __restrict__ x) {
    const int n4 = T * H / 4;
    for (int i = blockIdx.x * blockDim.x + threadIdx.x; i < n4;
         i += gridDim.x * blockDim.x) {
        float4 a = ((const float4*)x)[i];
        uint2 p; p.x = h2u(__floats2half2_rn(a.x, a.y));
        p.y = h2u(__floats2half2_rn(a.z, a.w));
        ((uint2*)g_xh)[i] = p;
    }
    if (blockIdx.x == 0 && threadIdx.x < E) g_cnt[threadIdx.x] = 0;
}

// ---------------- kernel: router --------------------------------------------
__global__ void k_router(const float* __restrict__ x, const float* __restrict__ gw) {
    int warp = (blockIdx.x * blockDim.x + threadIdx.x) >> 5;
    int lane = threadIdx.x & 31;
    if (warp >= T) return;
    const float* xr = x + (size_t)warp * H;
    float logit[E];
#pragma unroll
    for (int e = 0; e < E; e++) {
        const float* g = gw + (size_t)e * H;
        float p = 0.0f;
        for (int k = lane; k < H; k += 32) p += xr[k] * g[k];
#pragma unroll
        for (int o = 16; o; o >>= 1) p += __shfl_xor_sync(0xffffffffu, p, o);
        logit[e] = p;
    }
    if (lane == 0) {
        int i0 = 0; float v0 = logit[0];
#pragma unroll
        for (int e = 1; e < E; e++)
            if (logit[e] > v0) { v0 = logit[e]; i0 = e; }
        int i1 = -1; float v1 = -3.0e38f;
#pragma unroll
        for (int e = 0; e < E; e++)
            if (e != i0 && logit[e] > v1) { v1 = logit[e]; i1 = e; }
        float w0 = 1.0f / (1.0f + expf(v1 - v0));
        float w1 = 1.0f - w0;
        int p0 = atomicAdd(&g_cnt[i0], 1);
        g_tok[i0 * T + p0] = warp; g_wt[i0 * T + p0] = w0;
        g_inv[2 * warp + 0] = i0 * T + p0;
        int p1 = atomicAdd(&g_cnt[i1], 1);
        g_tok[i1 * T + p1] = warp; g_wt[i1 * T + p1] = w1;
        g_inv[2 * warp + 1] = i1 * T + p1;
    }
}

// ---------------- kernel: GEMM1 (fp16 mma): SwiGLU -> g_hh ------------------
// grid (F/64, T/128, E), block 256. Block tile 128x64 (g and u). Warp 32x32.
__global__ __launch_bounds__(256, 2)
void k_gemm1() {
    int e = blockIdx.z;
    int cnt = g_cnt[e];
    int m0 = blockIdx.y * 128;
    if (m0 >= cnt) return;
    int n0 = blockIdx.x * 64;

    extern __shared__ char sm[];
    int* toks = (int*)sm;
    uint32_t sb = smem_u32(sm);

    int tid = threadIdx.x, wid = tid >> 5, lane = tid & 31;
    int wm = (wid & 3) * 32, wn = (wid >> 2) * 32;
    int lr = lane >> 2, lc = lane & 3;
    int lq = lane >> 3, lrr = lane & 7;         // ldsm B: group, row-in-group

    if (tid < 128) toks[tid] = g_tok[e * T + min(m0 + tid, cnt - 1)];
    __syncthreads();

    const __half* w1e = g_w1h + ((size_t)e * F + n0) * H;
    const __half* w3e = g_w3h + ((size_t)e * F + n0) * H;

    float accG[2][4][4] = {};
    float accU[2][4][4] = {};

    // stage layout: A rows [0,128) at abase, B1 rows [0,64) then B2 rows [0,64)
    auto load_tile = [&](int s, int itile) {
        uint32_t abase = sb + TILE0 + s * STAGE_B;
        uint32_t bbase = abase + A_BYTES;
        int k0 = itile * BK;
#pragma unroll
        for (int q = 0; q < 2; q++) {
            int ch = tid + q * 256;
            int r = ch >> 2, c = ch & 3;
            cpa16(abase + r * 80 + c * 16, g_xh + (size_t)toks[r] * H + k0 + c * 8);
        }
#pragma unroll
        for (int q = 0; q < 2; q++) {
            int ch = tid + q * 256;
            int half_sel = ch >> 8;              // 0: B1, 1: B2
            int r = (ch >> 2) & 63, c = ch & 3;
            const __half* src = half_sel ? (w3e + (size_t)r * H + k0 + c * 8)
                                         : (w1e + (size_t)r * H + k0 + c * 8);
            cpa16(bbase + half_sel * (64 * 80) + r * 80 + c * 16, src);
        }
    };

    load_tile(0, 0); CP_COMMIT();
    load_tile(1, 1); CP_COMMIT();

    const int NIT = H / BK;   // 32
    for (int it = 0; it < NIT; ++it) {
        CP_WAIT1();
        __syncthreads();                 // single barrier per iter (S=3 safe)
        if (it + 2 < NIT) load_tile((it + 2) % S, it + 2);
        CP_COMMIT();

        uint32_t abase = sb + TILE0 + (it % S) * STAGE_B;
        uint32_t bbase = abase + A_BYTES;
#pragma unroll
        for (int kk = 0; kk < BK; kk += 16) {
            unsigned a[2][4];
#pragma unroll
            for (int i = 0; i < 2; i++) {
                uint32_t ad = abase + (wm + i * 16 + (lane & 15)) * 80
                            + kk * 2 + ((lane >> 4) << 4);
                ldsm4(a[i], ad);
            }
            // B fragments via ldmatrix.x4: jp covers (j=2jp, j=2jp+1)
            unsigned b1f[2][4], b2f[2][4];
#pragma unroll
            for (int jp = 0; jp < 2; jp++) {
                int nrow = wn + jp * 16 + (lq >> 1) * 8 + lrr;
                uint32_t koff = (uint32_t)((kk + (lq & 1) * 8) * 2);
                ldsm4(b1f[jp], bbase + nrow * 80 + koff);
                ldsm4(b2f[jp], bbase + 64 * 80 + nrow * 80 + koff);
            }
#pragma unroll
            for (int jp = 0; jp < 2; jp++) {
#pragma unroll
                for (int jj = 0; jj < 2; jj++) {
                    int j = jp * 2 + jj;
                    unsigned b1[2] = { b1f[jp][jj * 2], b1f[jp][jj * 2 + 1] };
                    unsigned b2[2] = { b2f[jp][jj * 2], b2f[jp][jj * 2 + 1] };
#pragma unroll
                    for (int i = 0; i < 2; i++) {
                        mma_f16(accG[i][j], a[i], b1);
                        mma_f16(accU[i][j], a[i], b2);
                    }
                }
            }
        }
    }

    // epilogue: h = silu(g)*u -> fp16
#pragma unroll
    for (int i = 0; i < 2; i++) {
#pragma unroll
        for (int p = 0; p < 2; p++) {
            int rr = wm + i * 16 + p * 8 + lr;
            size_t row = (size_t)(e * T + m0 + rr) * F + n0;
#pragma unroll
            for (int j = 0; j < 4; j++) {
                float g0 = accG[i][j][p * 2 + 0], g1 = accG[i][j][p * 2 + 1];
                float u0 = accU[i][j][p * 2 + 0], u1 = accU[i][j][p * 2 + 1];
                float h0 = g0 / (1.0f + __expf(-g0)) * u0;
                float h1 = g1 / (1.0f + __expf(-g1)) * u1;
                *(__half2*)&g_hh[row + wn + j * 8 + 2 * lc] = __floats2half2_rn(h0, h1);
            }
        }
    }
}

// ---------------- kernel: GEMM2 (fp16 mma): y = h @ w2^T --------------------
// grid (H/128, T/128, E), block 256. Block tile 128x128. Warp 64x32.
__global__ __launch_bounds__(256, 2)
void k_gemm2() {
    int e = blockIdx.z;
    int cnt = g_cnt[e];
    int m0 = blockIdx.y * 128;
    if (m0 >= cnt) return;
    int n0 = blockIdx.x * 128;

    extern __shared__ char sm[];
    uint32_t sb = smem_u32(sm);

    int tid = threadIdx.x, wid = tid >> 5, lane = tid & 31;
    int wm = (wid & 1) * 64, wn = (wid >> 1) * 32;
    int lr = lane >> 2, lc = lane & 3;
    int lq = lane >> 3, lrr = lane & 7;

    const __half* hbase = g_hh + (size_t)(e * T + m0) * F;
    const __half* w2e   = g_w2h + ((size_t)e * H + n0) * F;

    float acc[4][4][4] = {};

    auto load_tile = [&](int s, int itile) {
        uint32_t abase = sb + TILE0 + s * STAGE_B;
        uint32_t bbase = abase + A_BYTES;
        int k0 = itile * BK;
#pragma unroll
        for (int q = 0; q < 2; q++) {
            int ch = tid + q * 256;
            int r = ch >> 2, c = ch & 3;
            cpa16(abase + r * 80 + c * 16, hbase + (size_t)r * F + k0 + c * 8);
            cpa16(bbase + r * 80 + c * 16, w2e + (size_t)r * F + k0 + c * 8);
        }
    };

    load_tile(0, 0); CP_COMMIT();
    load_tile(1, 1); CP_COMMIT();

    const int NIT = F / BK;   // 88
    for (int it = 0; it < NIT; ++it) {
        CP_WAIT1();
        __syncthreads();                 // single barrier per iter (S=3 safe)
        if (it + 2 < NIT) load_tile((it + 2) % S, it + 2);
        CP_COMMIT();

        uint32_t abase = sb + TILE0 + (it % S) * STAGE_B;
        uint32_t bbase = abase + A_BYTES;
#pragma unroll
        for (int kk = 0; kk < BK; kk += 16) {
            unsigned a[4][4];
#pragma unroll
            for (int i = 0; i < 4; i++) {
                uint32_t ad = abase + (wm + i * 16 + (lane & 15)) * 80
                            + kk * 2 + ((lane >> 4) << 4);
                ldsm4(a[i], ad);
            }
            unsigned bf[2][4];
#pragma unroll
            for (int jp = 0; jp < 2; jp++) {
                int nrow = wn + jp * 16 + (lq >> 1) * 8 + lrr;
                uint32_t koff = (uint32_t)((kk + (lq & 1) * 8) * 2);
                ldsm4(bf[jp], bbase + nrow * 80 + koff);
            }
#pragma unroll
            for (int jp = 0; jp < 2; jp++) {
#pragma unroll
                for (int jj = 0; jj < 2; jj++) {
                    int j = jp * 2 + jj;
                    unsigned b[2] = { bf[jp][jj * 2], bf[jp][jj * 2 + 1] };
#pragma unroll
                    for (int i = 0; i < 4; i++) mma_f16(acc[i][j], a[i], b);
                }
            }
        }
    }

    // epilogue: plain stores of unweighted y (combine kernel applies weights)
#pragma unroll
    for (int i = 0; i < 4; i++) {
#pragma unroll
        for (int p = 0; p < 2; p++) {
            int rr = wm + i * 16 + p * 8 + lr;
            size_t row = (size_t)(e * T + m0 + rr) * H + n0;
#pragma unroll
            for (int j = 0; j < 4; j++) {
                float2 st;
                st.x = acc[i][j][p * 2 + 0];
                st.y = acc[i][j][p * 2 + 1];
                *(float2*)&g_y[row + wn + j * 8 + 2 * lc] = st;
            }
        }
    }
}

// ---------------- kernel: combine (out = w0*y[s0] + w1*y[s1]) ---------------
__global__ void k_combine(float* __restrict__ out) {
    int idx = blockIdx.x * blockDim.x + threadIdx.x;   // one float4
    if (idx >= T * H / 4) return;
    int t = idx / (H / 4);
    int c = idx % (H / 4);
    int s0 = g_inv[2 * t], s1 = g_inv[2 * t + 1];
    float w0 = g_wt[s0], w1 = g_wt[s1];
    float4 a = *(const float4*)&g_y[(size_t)s0 * H + c * 4];
    float4 b = *(const float4*)&g_y[(size_t)s1 * H + c * 4];
    float4 o;
    o.x = w0 * a.x + w1 * b.x;
    o.y = w0 * a.y + w1 * b.y;
    o.z = w0 * a.z + w1 * b.z;
    o.w = w0 * a.w + w1 * b.w;
    ((float4*)out)[idx] = o;
}

// ---------------- launch ----------------------------------------------------
extern "C" void kernel_launch(void* const* d_in, const int* in_sizes, int n_in,
                              void* d_out, int out_size) {
    const float* x  = (const float*)d_in[0];   // [T, H]
    const float* gw = (const float*)d_in[1];   // [E, H]
    const float* w1 = (const float*)d_in[2];   // [E, F, H]
    const float* w3 = (const float*)d_in[3];   // [E, F, H]
    const float* w2 = (const float*)d_in[4];   // [E, H, F]
    float* out = (float*)d_out;                // [T, H]

    cudaFuncSetAttribute(k_gemm1, cudaFuncAttributeMaxDynamicSharedMemorySize, SMEM_SZ);
    cudaFuncSetAttribute(k_gemm2, cudaFuncAttributeMaxDynamicSharedMemorySize, SMEM_SZ);

    k_init<<<256, 256>>>(x);
    k_router<<<T / 8, 256>>>(x, gw);
    k_prep<<<1024, 256>>>(w1, w3, w2);
    dim3 g1(F / 64, T / 128, E);
    k_gemm1<<<g1, 256, SMEM_SZ>>>();
    dim3 g2(H / 128, T / 128, E);
    k_gemm2<<<g2, 256, SMEM_SZ>>>();
    k_combine<<<(T * H / 4 + 255) / 256, 256>>>(out);
}